// round 3
// baseline (speedup 1.0000x reference)
#include <cuda_runtime.h>
#include <math.h>

#define D     1024
#define NV    128
#define BATCH 32768

// Scratch (static device globals)
__device__ float g_U   [D * NV];      // normalized reflectors fp32, U[d*NV+k]
__device__ float g_Utf [D * NV];      // tf32 bits of U   (stage1 B)
__device__ float g_Uttf[NV * D];      // tf32 bits of U^T (stage3 B)
__device__ float g_Gp  [2 * NV * NV]; // Gram partials (K-split by 2)
__device__ float g_Mtf [NV * NV];     // tf32 bits of M = 2T

__device__ __forceinline__ unsigned f2tf(float f) {
    unsigned r;
    asm("cvt.rna.tf32.f32 %0, %1;" : "=r"(r) : "f"(f));
    return r;
}

// ---------------------------------------------------------------------------
// Kernel 1: normalize columns of v -> U (fp32) + tf32-bit copies (U, U^T)
// grid 4, block (32, 8): lane = column k, ty = d-slice
// ---------------------------------------------------------------------------
__global__ void k_norm(const float* __restrict__ v) {
    const int k  = blockIdx.x * 32 + threadIdx.x;
    const int ty = threadIdx.y;
    __shared__ float part[8][33];
    __shared__ float sinv[32];

    float s = 0.f;
    const int d0 = ty * 128;
    for (int d = d0; d < d0 + 128; d++) {
        float t = v[d * NV + k];
        s += t * t;
    }
    part[ty][threadIdx.x] = s;
    __syncthreads();
    if (ty == 0) {
        float tot = 0.f;
#pragma unroll
        for (int q = 0; q < 8; q++) tot += part[q][threadIdx.x];
        sinv[threadIdx.x] = 1.f / sqrtf(tot);
    }
    __syncthreads();
    const float inv = sinv[threadIdx.x];
    for (int d = d0; d < d0 + 128; d++) {
        float u = v[d * NV + k] * inv;
        g_U[d * NV + k] = u;
        float ub = __uint_as_float(f2tf(u));
        g_Utf [d * NV + k] = ub;
        g_Uttf[k * D  + d] = ub;
    }
}

// ---------------------------------------------------------------------------
// Kernel 2: Gram partials. grid (16,2), 128 threads.
// Block (jb, s): columns jb*8..+7, d-range [s*512, s*512+512)
// ---------------------------------------------------------------------------
__global__ void k_gram() {
    const int i  = threadIdx.x;
    const int jb = blockIdx.x * 8;
    const int s  = blockIdx.y;
    float acc[8] = {0, 0, 0, 0, 0, 0, 0, 0};
    const int d0 = s * 512;
#pragma unroll 2
    for (int d = d0; d < d0 + 512; d++) {
        float ui = g_U[d * NV + i];
#pragma unroll
        for (int q = 0; q < 8; q++) acc[q] += ui * g_U[d * NV + jb + q];
    }
#pragma unroll
    for (int q = 0; q < 8; q++) g_Gp[s * NV * NV + i * NV + jb + q] = acc[q];
}

// ---------------------------------------------------------------------------
// Kernel 3: M = 2*(I + 2*strictupper(G))^{-1}, single CTA of 128 threads.
// Thread tid owns T-row tid exclusively -> zero __syncthreads in the loop.
// smem: sG[128*129] + sT[128*129]
// ---------------------------------------------------------------------------
__global__ void k_buildM() {
    extern __shared__ float sm[];
    float* sG = sm;
    float* sT = sm + 128 * 129;
    const int tid = threadIdx.x;

    for (int idx = tid; idx < NV * NV; idx += 128) {
        int r = idx >> 7, c = idx & 127;
        sG[r * 129 + c] = g_Gp[idx] + g_Gp[NV * NV + idx];
    }
    for (int j = 0; j < NV; j++)
        sT[tid * 129 + j] = (j == tid) ? 1.f : 0.f;
    __syncthreads();   // only sync: sG visible to all

    const float* myrow = &sT[tid * 129];
    for (int m = 1; m < NV; m++) {
        float a0 = 0.f, a1 = 0.f, a2 = 0.f, a3 = 0.f;
        int j = 0;
        for (; j + 4 <= m; j += 4) {
            a0 += myrow[j    ] * sG[(j    ) * 129 + m];
            a1 += myrow[j + 1] * sG[(j + 1) * 129 + m];
            a2 += myrow[j + 2] * sG[(j + 2) * 129 + m];
            a3 += myrow[j + 3] * sG[(j + 3) * 129 + m];
        }
        for (; j < m; j++) a0 += myrow[j] * sG[j * 129 + m];
        float acc = (a0 + a1) + (a2 + a3);
        if (tid < m) sT[tid * 129 + m] = -2.f * acc;
    }
    for (int j = 0; j < NV; j++)
        g_Mtf[tid * NV + j] = __uint_as_float(f2tf(2.f * sT[tid * 129 + j]));
}

// ---------------------------------------------------------------------------
// Fused tensor-core kernel (tf32 mma m16n8k8), all fragments pre-converted.
//   Stage1: Y = x U (K=1024)   Stage2: Z = Y M (K=128)   Stage3: out = x - Z U^T + b
// CTA: 128 rows, 256 threads, warp grid 2x4 (64x32 tiles).
// Strides: XS=36 (A clean), US=136 (B clean), YS=132 (A clean).
// ---------------------------------------------------------------------------
#define XS 36
#define US 136
#define YS 132

__device__ __forceinline__ void mma8(float c[4], const unsigned a[4], const unsigned b[2]) {
    asm volatile(
        "mma.sync.aligned.m16n8k8.row.col.f32.tf32.tf32.f32 "
        "{%0,%1,%2,%3}, {%4,%5,%6,%7}, {%8,%9}, {%0,%1,%2,%3};"
        : "+f"(c[0]), "+f"(c[1]), "+f"(c[2]), "+f"(c[3])
        : "r"(a[0]), "r"(a[1]), "r"(a[2]), "r"(a[3]), "r"(b[0]), "r"(b[1]));
}

__global__ __launch_bounds__(256, 2) void k_fused(const float* __restrict__ x,
                                                  const float* __restrict__ bias,
                                                  float* __restrict__ out) {
    extern __shared__ float smf[];
    float* xs = smf;              // 128*36  = 4608 (tf32 bits)
    float* us = smf + 4608;       // 32*136  = 4352 (tf32 bits)
    float* ys = smf + 8960;       // 128*132 = 16896 (tf32 bits)

    const int tid  = threadIdx.x;
    const int lane = tid & 31, wid = tid >> 5;
    const int wm = wid >> 2, wn = wid & 3;
    const int grp = lane >> 2, tg = lane & 3;
    const int rowBase = blockIdx.x * 128;
    const int wrow = wm * 64;
    const int wcol = wn * 32;

    const unsigned* xsu = (const unsigned*)xs;
    const unsigned* usu = (const unsigned*)us;
    const unsigned* ysu = (const unsigned*)ys;

    float acc[4][4][4];

    // x-tile thread mapping: row = q>>3 (4 rows per 32-lane grp of q), c4 = q&7
    const int xr0 = tid >> 3, xc4 = tid & 7;

    // ======== Stage 1: Y = x @ U ========
#pragma unroll
    for (int mf = 0; mf < 4; mf++)
#pragma unroll
        for (int nf = 0; nf < 4; nf++)
#pragma unroll
            for (int q = 0; q < 4; q++) acc[mf][nf][q] = 0.f;

    float4 p[4];
#pragma unroll
    for (int it = 0; it < 4; it++)
        p[it] = *(const float4*)&x[(size_t)(rowBase + xr0 + it * 32) * D + xc4 * 4];

    for (int kt = 0; kt < D / 32; kt++) {
        // U tile (already tf32 bits): issue LDGs first
        float4 ureg[4];
#pragma unroll
        for (int it = 0; it < 4; it++) {
            int q = tid + it * 256;
            int kr = q >> 5, c4 = q & 31;
            ureg[it] = *(const float4*)&g_Utf[(kt * 32 + kr) * NV + c4 * 4];
        }
        // x tile: cvt + store
#pragma unroll
        for (int it = 0; it < 4; it++) {
            uint4 t;
            t.x = f2tf(p[it].x); t.y = f2tf(p[it].y);
            t.z = f2tf(p[it].z); t.w = f2tf(p[it].w);
            *(uint4*)&xs[(xr0 + it * 32) * XS + xc4 * 4] = t;
        }
#pragma unroll
        for (int it = 0; it < 4; it++) {
            int q = tid + it * 256;
            int kr = q >> 5, c4 = q & 31;
            *(float4*)&us[kr * US + c4 * 4] = ureg[it];
        }
        __syncthreads();
        if (kt + 1 < D / 32) {
#pragma unroll
            for (int it = 0; it < 4; it++)
                p[it] = *(const float4*)&x[(size_t)(rowBase + xr0 + it * 32) * D +
                                           (kt + 1) * 32 + xc4 * 4];
        }
#pragma unroll
        for (int k8 = 0; k8 < 4; k8++) {
            const int kb = k8 * 8;
            unsigned A[4][4], B[4][2];
#pragma unroll
            for (int mf = 0; mf < 4; mf++) {
                int r = wrow + mf * 16 + grp;
                A[mf][0] = xsu[r * XS + kb + tg];
                A[mf][1] = xsu[(r + 8) * XS + kb + tg];
                A[mf][2] = xsu[r * XS + kb + tg + 4];
                A[mf][3] = xsu[(r + 8) * XS + kb + tg + 4];
            }
#pragma unroll
            for (int nf = 0; nf < 4; nf++) {
                int c = wcol + nf * 8 + grp;
                B[nf][0] = usu[(kb + tg) * US + c];
                B[nf][1] = usu[(kb + tg + 4) * US + c];
            }
#pragma unroll
            for (int mf = 0; mf < 4; mf++)
#pragma unroll
                for (int nf = 0; nf < 4; nf++)
                    mma8(acc[mf][nf], A[mf], B[nf]);
        }
        __syncthreads();
    }

    // Y -> ys (tf32 bits)
#pragma unroll
    for (int mf = 0; mf < 4; mf++)
#pragma unroll
        for (int nf = 0; nf < 4; nf++) {
            int r = wrow + mf * 16 + grp, c = wcol + nf * 8 + tg * 2;
            ys[r * YS + c]           = __uint_as_float(f2tf(acc[mf][nf][0]));
            ys[r * YS + c + 1]       = __uint_as_float(f2tf(acc[mf][nf][1]));
            ys[(r + 8) * YS + c]     = __uint_as_float(f2tf(acc[mf][nf][2]));
            ys[(r + 8) * YS + c + 1] = __uint_as_float(f2tf(acc[mf][nf][3]));
        }
    __syncthreads();

    // ======== Stage 2: Z = Y @ M ========
#pragma unroll
    for (int mf = 0; mf < 4; mf++)
#pragma unroll
        for (int nf = 0; nf < 4; nf++)
#pragma unroll
            for (int q = 0; q < 4; q++) acc[mf][nf][q] = 0.f;

    for (int mt = 0; mt < 4; mt++) {
#pragma unroll
        for (int it = 0; it < 4; it++) {
            int q = tid + it * 256;
            int kr = q >> 5, c4 = q & 31;
            *(float4*)&us[kr * US + c4 * 4] =
                *(const float4*)&g_Mtf[(mt * 32 + kr) * NV + c4 * 4];
        }
        __syncthreads();
#pragma unroll
        for (int k8 = 0; k8 < 4; k8++) {
            const int kb = k8 * 8;
            const int kg = mt * 32 + kb;
            unsigned A[4][4], B[4][2];
#pragma unroll
            for (int mf = 0; mf < 4; mf++) {
                int r = wrow + mf * 16 + grp;
                A[mf][0] = ysu[r * YS + kg + tg];
                A[mf][1] = ysu[(r + 8) * YS + kg + tg];
                A[mf][2] = ysu[r * YS + kg + tg + 4];
                A[mf][3] = ysu[(r + 8) * YS + kg + tg + 4];
            }
#pragma unroll
            for (int nf = 0; nf < 4; nf++) {
                int c = wcol + nf * 8 + grp;
                B[nf][0] = usu[(kb + tg) * US + c];
                B[nf][1] = usu[(kb + tg + 4) * US + c];
            }
#pragma unroll
            for (int mf = 0; mf < 4; mf++)
#pragma unroll
                for (int nf = 0; nf < 4; nf++)
                    mma8(acc[mf][nf], A[mf], B[nf]);
        }
        __syncthreads();
    }

    // Z overwrites Y (tf32 bits)
#pragma unroll
    for (int mf = 0; mf < 4; mf++)
#pragma unroll
        for (int nf = 0; nf < 4; nf++) {
            int r = wrow + mf * 16 + grp, c = wcol + nf * 8 + tg * 2;
            ys[r * YS + c]           = __uint_as_float(f2tf(acc[mf][nf][0]));
            ys[r * YS + c + 1]       = __uint_as_float(f2tf(acc[mf][nf][1]));
            ys[(r + 8) * YS + c]     = __uint_as_float(f2tf(acc[mf][nf][2]));
            ys[(r + 8) * YS + c + 1] = __uint_as_float(f2tf(acc[mf][nf][3]));
        }
    __syncthreads();

    // ======== Stage 3: out = x - Z @ U^T + b ========
    for (int dB = 0; dB < D; dB += 128) {
#pragma unroll
        for (int mf = 0; mf < 4; mf++)
#pragma unroll
            for (int nf = 0; nf < 4; nf++)
#pragma unroll
                for (int q = 0; q < 4; q++) acc[mf][nf][q] = 0.f;

        for (int mt = 0; mt < 4; mt++) {
            float4 ureg[4];
#pragma unroll
            for (int it = 0; it < 4; it++) {
                int q = tid + it * 256;
                int kr = q >> 5, c4 = q & 31;
                ureg[it] = *(const float4*)&g_Uttf[(size_t)(mt * 32 + kr) * D + dB + c4 * 4];
            }
#pragma unroll
            for (int it = 0; it < 4; it++) {
                int q = tid + it * 256;
                int kr = q >> 5, c4 = q & 31;
                *(float4*)&us[kr * US + c4 * 4] = ureg[it];
            }
            __syncthreads();
#pragma unroll
            for (int k8 = 0; k8 < 4; k8++) {
                const int kb = k8 * 8;
                const int kg = mt * 32 + kb;
                unsigned A[4][4], B[4][2];
#pragma unroll
                for (int mf = 0; mf < 4; mf++) {
                    int r = wrow + mf * 16 + grp;
                    A[mf][0] = ysu[r * YS + kg + tg];
                    A[mf][1] = ysu[(r + 8) * YS + kg + tg];
                    A[mf][2] = ysu[r * YS + kg + tg + 4];
                    A[mf][3] = ysu[(r + 8) * YS + kg + tg + 4];
                }
#pragma unroll
                for (int nf = 0; nf < 4; nf++) {
                    int c = wcol + nf * 8 + grp;
                    B[nf][0] = usu[(kb + tg) * US + c];
                    B[nf][1] = usu[(kb + tg + 4) * US + c];
                }
#pragma unroll
                for (int mf = 0; mf < 4; mf++)
#pragma unroll
                    for (int nf = 0; nf < 4; nf++)
                        mma8(acc[mf][nf], A[mf], B[nf]);
            }
            __syncthreads();
        }

        // epilogue: out = x + b - acc
#pragma unroll
        for (int mf = 0; mf < 4; mf++)
#pragma unroll
            for (int nf = 0; nf < 4; nf++) {
                int r = rowBase + wrow + mf * 16 + grp;
                int c = dB + wcol + nf * 8 + tg * 2;
                float2 bv = *(const float2*)&bias[c];
                float2 x0 = *(const float2*)&x[(size_t)r * D + c];
                float2 x1 = *(const float2*)&x[(size_t)(r + 8) * D + c];
                float2 o0, o1;
                o0.x = x0.x + bv.x - acc[mf][nf][0];
                o0.y = x0.y + bv.y - acc[mf][nf][1];
                o1.x = x1.x + bv.x - acc[mf][nf][2];
                o1.y = x1.y + bv.y - acc[mf][nf][3];
                *(float2*)&out[(size_t)r * D + c]       = o0;
                *(float2*)&out[(size_t)(r + 8) * D + c] = o1;
            }
    }
}

// ---------------------------------------------------------------------------
extern "C" void kernel_launch(void* const* d_in, const int* in_sizes, int n_in,
                              void* d_out, int out_size) {
    const float* x = nullptr;
    const float* v = nullptr;
    const float* b = nullptr;
    for (int i = 0; i < n_in; i++) {
        if      (in_sizes[i] == BATCH * D) x = (const float*)d_in[i];
        else if (in_sizes[i] == D * NV)    v = (const float*)d_in[i];
        else if (in_sizes[i] == D)         b = (const float*)d_in[i];
    }
    float* out = (float*)d_out;

    const size_t smemM     = 2 * 128 * 129 * sizeof(float);            // 132 KB
    const size_t smemFused = (4608 + 4352 + 16896) * sizeof(float);    // ~103.4 KB
    cudaFuncSetAttribute(k_buildM, cudaFuncAttributeMaxDynamicSharedMemorySize, (int)smemM);
    cudaFuncSetAttribute(k_fused,  cudaFuncAttributeMaxDynamicSharedMemorySize, (int)smemFused);

    k_norm  <<<4, dim3(32, 8)>>>(v);
    k_gram  <<<dim3(16, 2), 128>>>();
    k_buildM<<<1, 128, smemM>>>();
    k_fused <<<BATCH / 128, 256, smemFused>>>(x, b, out);
}

// round 4
// speedup vs baseline: 1.1073x; 1.1073x over previous
#include <cuda_runtime.h>
#include <math.h>

#define D     1024
#define NV    128
#define BATCH 32768

// Scratch (static device globals)
__device__ float g_Utf [D * NV];      // tf32 bits of normalized U   (stage1 B)
__device__ float g_Uttf[NV * D];      // tf32 bits of U^T            (stage3 B)
__device__ float g_csq [128 * NV];    // column sum-of-squares partials [blk][col]
__device__ float g_Gp  [8 * NV * NV]; // Gram partials (K-split by 8)
__device__ float g_Mtf [NV * NV];     // tf32 bits of M = 2T

__device__ __forceinline__ unsigned f2tf(float f) {
    unsigned r;
    asm("cvt.rna.tf32.f32 %0, %1;" : "=r"(r) : "f"(f));
    return r;
}

// ---------------------------------------------------------------------------
// Setup A: column sum-of-squares partials. grid 128, block 128.
// Block b handles rows b*8..b*8+7; fully coalesced; deterministic (no atomics).
// ---------------------------------------------------------------------------
__global__ void k_colsq(const float* __restrict__ v) {
    const int col = threadIdx.x;
    const int r0  = blockIdx.x * 8;
    float s = 0.f;
#pragma unroll
    for (int r = 0; r < 8; r++) {
        float t = v[(r0 + r) * NV + col];
        s += t * t;
    }
    g_csq[blockIdx.x * NV + col] = s;
}

// ---------------------------------------------------------------------------
// Setup B: normalize + tf32-convert + transpose. grid (8,4), block (32,8).
// Tile: 128 rows x 32 cols. Coalesced v reads, coalesced Utf/Uttf writes.
// ---------------------------------------------------------------------------
__global__ void k_prep(const float* __restrict__ v) {
    const int tx = threadIdx.x, ty = threadIdx.y;
    const int tid = ty * 32 + tx;
    const int d0 = blockIdx.x * 128;
    const int k0 = blockIdx.y * 32;

    __shared__ float part[8][33];
    __shared__ float sinv[32];
    __shared__ float tile[32 * 137];   // [col-local][row-local], pad 137

    // reduce column sumsq partials for this block's 32 columns
    float ps = 0.f;
    for (int s = ty; s < 128; s += 8) ps += g_csq[s * NV + k0 + tx];
    part[ty][tx] = ps;
    __syncthreads();
    if (ty == 0) {
        float tot = 0.f;
#pragma unroll
        for (int q = 0; q < 8; q++) tot += part[q][tx];
        sinv[tx] = rsqrtf(tot);
    }
    __syncthreads();
    const float inv = sinv[tx];

#pragma unroll
    for (int rr = 0; rr < 16; rr++) {
        int dd = ty * 16 + rr;
        int d  = d0 + dd;
        float u = v[d * NV + k0 + tx] * inv;
        float ub = __uint_as_float(f2tf(u));
        g_Utf[d * NV + k0 + tx] = ub;
        tile[tx * 137 + dd] = ub;
    }
    __syncthreads();

    for (int e = tid; e < 32 * 128; e += 256) {
        int kl = e >> 7, dd = e & 127;
        g_Uttf[(size_t)(k0 + kl) * D + d0 + dd] = tile[kl * 137 + dd];
    }
}

// ---------------------------------------------------------------------------
// Setup C: Gram partials G = Utf^T Utf. grid (16 colblocks, 8 ksplit), 128 thr.
// ---------------------------------------------------------------------------
__global__ void k_gram() {
    const int i  = threadIdx.x;
    const int jb = blockIdx.x * 8;
    const int s  = blockIdx.y;
    float acc[8] = {0, 0, 0, 0, 0, 0, 0, 0};
    const int d0 = s * 128;
#pragma unroll 2
    for (int d = d0; d < d0 + 128; d++) {
        float ui = g_Utf[d * NV + i];
#pragma unroll
        for (int q = 0; q < 8; q++) acc[q] += ui * g_Utf[d * NV + jb + q];
    }
#pragma unroll
    for (int q = 0; q < 8; q++) g_Gp[s * NV * NV + i * NV + jb + q] = acc[q];
}

// ---------------------------------------------------------------------------
// Setup D: M = 2*T via WY recurrence. Single CTA, 128 threads, row-parallel.
// Row tid of T is zero left of diag, 1 at diag -> inner loop starts at j=tid.
// ---------------------------------------------------------------------------
__global__ void k_buildM() {
    extern __shared__ float sm[];
    float* sG = sm;              // 128*129
    float* sT = sm + 128 * 129;  // 128*129
    const int tid = threadIdx.x;

    for (int idx = tid; idx < NV * NV; idx += 128) {
        int r = idx >> 7, c = idx & 127;
        float g = 0.f;
#pragma unroll
        for (int s = 0; s < 8; s++) g += g_Gp[s * NV * NV + idx];
        sG[r * 129 + c] = g;
    }
    for (int j = 0; j < NV; j++)
        sT[tid * 129 + j] = (j == tid) ? 1.f : 0.f;
    __syncthreads();

    const float* myrow = &sT[tid * 129];
    for (int m = 1; m < NV; m++) {
        if (tid < m) {
            float a0 = 0.f, a1 = 0.f, a2 = 0.f, a3 = 0.f;
            int j = tid;
            for (; j + 4 <= m; j += 4) {
                a0 += myrow[j    ] * sG[(j    ) * 129 + m];
                a1 += myrow[j + 1] * sG[(j + 1) * 129 + m];
                a2 += myrow[j + 2] * sG[(j + 2) * 129 + m];
                a3 += myrow[j + 3] * sG[(j + 3) * 129 + m];
            }
            for (; j < m; j++) a0 += myrow[j] * sG[j * 129 + m];
            sT[tid * 129 + m] = -2.f * ((a0 + a1) + (a2 + a3));
        }
    }
    for (int j = 0; j < NV; j++)
        g_Mtf[tid * NV + j] = __uint_as_float(f2tf(2.f * sT[tid * 129 + j]));
}

// ---------------------------------------------------------------------------
// Fused tensor-core kernel (tf32 mma m16n8k8), all operands pre-converted,
// all B-tiles prefetched behind compute.
// ---------------------------------------------------------------------------
#define XS 36
#define US 136
#define YS 132

__device__ __forceinline__ void mma8(float c[4], const unsigned a[4], const unsigned b[2]) {
    asm volatile(
        "mma.sync.aligned.m16n8k8.row.col.f32.tf32.tf32.f32 "
        "{%0,%1,%2,%3}, {%4,%5,%6,%7}, {%8,%9}, {%0,%1,%2,%3};"
        : "+f"(c[0]), "+f"(c[1]), "+f"(c[2]), "+f"(c[3])
        : "r"(a[0]), "r"(a[1]), "r"(a[2]), "r"(a[3]), "r"(b[0]), "r"(b[1]));
}

__global__ __launch_bounds__(256, 2) void k_fused(const float* __restrict__ x,
                                                  const float* __restrict__ bias,
                                                  float* __restrict__ out) {
    extern __shared__ float smf[];
    float* xs = smf;              // 128*36  = 4608
    float* us = smf + 4608;       // 32*136  = 4352
    float* ys = smf + 8960;       // 128*132 = 16896

    const int tid  = threadIdx.x;
    const int lane = tid & 31, wid = tid >> 5;
    const int wm = wid >> 2, wn = wid & 3;
    const int grp = lane >> 2, tg = lane & 3;
    const int rowBase = blockIdx.x * 128;
    const int wrow = wm * 64;
    const int wcol = wn * 32;

    const unsigned* xsu = (const unsigned*)xs;
    const unsigned* usu = (const unsigned*)us;
    const unsigned* ysu = (const unsigned*)ys;

    float acc[4][4][4];
    const int xr0 = tid >> 3, xc4 = tid & 7;
    const int ukr = tid >> 5, uc4 = tid & 31;   // U/M tile mapping (per it +8 rows)

    // ======== Stage 1: Y = x @ U ========
#pragma unroll
    for (int mf = 0; mf < 4; mf++)
#pragma unroll
        for (int nf = 0; nf < 4; nf++)
#pragma unroll
            for (int q = 0; q < 4; q++) acc[mf][nf][q] = 0.f;

    float4 p[4], ureg[4];
#pragma unroll
    for (int it = 0; it < 4; it++) {
        p[it] = *(const float4*)&x[(size_t)(rowBase + xr0 + it * 32) * D + xc4 * 4];
        ureg[it] = *(const float4*)&g_Utf[(ukr + it * 8) * NV + uc4 * 4];
    }

    for (int kt = 0; kt < D / 32; kt++) {
#pragma unroll
        for (int it = 0; it < 4; it++) {
            uint4 t;
            t.x = f2tf(p[it].x); t.y = f2tf(p[it].y);
            t.z = f2tf(p[it].z); t.w = f2tf(p[it].w);
            *(uint4*)&xs[(xr0 + it * 32) * XS + xc4 * 4] = t;
        }
#pragma unroll
        for (int it = 0; it < 4; it++)
            *(float4*)&us[(ukr + it * 8) * US + uc4 * 4] = ureg[it];
        __syncthreads();
        if (kt + 1 < D / 32) {
#pragma unroll
            for (int it = 0; it < 4; it++) {
                p[it] = *(const float4*)&x[(size_t)(rowBase + xr0 + it * 32) * D +
                                           (kt + 1) * 32 + xc4 * 4];
                ureg[it] = *(const float4*)&g_Utf[((kt + 1) * 32 + ukr + it * 8) * NV + uc4 * 4];
            }
        }
#pragma unroll
        for (int k8 = 0; k8 < 4; k8++) {
            const int kb = k8 * 8;
            unsigned A[4][4], B[4][2];
#pragma unroll
            for (int mf = 0; mf < 4; mf++) {
                int r = wrow + mf * 16 + grp;
                A[mf][0] = xsu[r * XS + kb + tg];
                A[mf][1] = xsu[(r + 8) * XS + kb + tg];
                A[mf][2] = xsu[r * XS + kb + tg + 4];
                A[mf][3] = xsu[(r + 8) * XS + kb + tg + 4];
            }
#pragma unroll
            for (int nf = 0; nf < 4; nf++) {
                int c = wcol + nf * 8 + grp;
                B[nf][0] = usu[(kb + tg) * US + c];
                B[nf][1] = usu[(kb + tg + 4) * US + c];
            }
#pragma unroll
            for (int mf = 0; mf < 4; mf++)
#pragma unroll
                for (int nf = 0; nf < 4; nf++)
                    mma8(acc[mf][nf], A[mf], B[nf]);
        }
        __syncthreads();
    }

    // Y -> ys (tf32 bits)
#pragma unroll
    for (int mf = 0; mf < 4; mf++)
#pragma unroll
        for (int nf = 0; nf < 4; nf++) {
            int r = wrow + mf * 16 + grp, c = wcol + nf * 8 + tg * 2;
            ys[r * YS + c]           = __uint_as_float(f2tf(acc[mf][nf][0]));
            ys[r * YS + c + 1]       = __uint_as_float(f2tf(acc[mf][nf][1]));
            ys[(r + 8) * YS + c]     = __uint_as_float(f2tf(acc[mf][nf][2]));
            ys[(r + 8) * YS + c + 1] = __uint_as_float(f2tf(acc[mf][nf][3]));
        }

    // ======== Stage 2: Z = Y @ M ========
#pragma unroll
    for (int mf = 0; mf < 4; mf++)
#pragma unroll
        for (int nf = 0; nf < 4; nf++)
#pragma unroll
            for (int q = 0; q < 4; q++) acc[mf][nf][q] = 0.f;

#pragma unroll
    for (int it = 0; it < 4; it++)
        ureg[it] = *(const float4*)&g_Mtf[(ukr + it * 8) * NV + uc4 * 4];

    for (int mt = 0; mt < 4; mt++) {
        __syncthreads();   // also covers Y->ys visibility at mt=0
#pragma unroll
        for (int it = 0; it < 4; it++)
            *(float4*)&us[(ukr + it * 8) * US + uc4 * 4] = ureg[it];
        __syncthreads();
        if (mt + 1 < 4) {
#pragma unroll
            for (int it = 0; it < 4; it++)
                ureg[it] = *(const float4*)&g_Mtf[((mt + 1) * 32 + ukr + it * 8) * NV + uc4 * 4];
        }
#pragma unroll
        for (int k8 = 0; k8 < 4; k8++) {
            const int kb = k8 * 8;
            const int kg = mt * 32 + kb;
            unsigned A[4][4], B[4][2];
#pragma unroll
            for (int mf = 0; mf < 4; mf++) {
                int r = wrow + mf * 16 + grp;
                A[mf][0] = ysu[r * YS + kg + tg];
                A[mf][1] = ysu[(r + 8) * YS + kg + tg];
                A[mf][2] = ysu[r * YS + kg + tg + 4];
                A[mf][3] = ysu[(r + 8) * YS + kg + tg + 4];
            }
#pragma unroll
            for (int nf = 0; nf < 4; nf++) {
                int c = wcol + nf * 8 + grp;
                B[nf][0] = usu[(kb + tg) * US + c];
                B[nf][1] = usu[(kb + tg + 4) * US + c];
            }
#pragma unroll
            for (int mf = 0; mf < 4; mf++)
#pragma unroll
                for (int nf = 0; nf < 4; nf++)
                    mma8(acc[mf][nf], A[mf], B[nf]);
        }
    }
    __syncthreads();

    // Z overwrites Y (tf32 bits)
#pragma unroll
    for (int mf = 0; mf < 4; mf++)
#pragma unroll
        for (int nf = 0; nf < 4; nf++) {
            int r = wrow + mf * 16 + grp, c = wcol + nf * 8 + tg * 2;
            ys[r * YS + c]           = __uint_as_float(f2tf(acc[mf][nf][0]));
            ys[r * YS + c + 1]       = __uint_as_float(f2tf(acc[mf][nf][1]));
            ys[(r + 8) * YS + c]     = __uint_as_float(f2tf(acc[mf][nf][2]));
            ys[(r + 8) * YS + c + 1] = __uint_as_float(f2tf(acc[mf][nf][3]));
        }

    // ======== Stage 3: out = x - Z @ U^T + b ========
    for (int dB = 0; dB < D; dB += 128) {
#pragma unroll
        for (int mf = 0; mf < 4; mf++)
#pragma unroll
            for (int nf = 0; nf < 4; nf++)
#pragma unroll
                for (int q = 0; q < 4; q++) acc[mf][nf][q] = 0.f;

#pragma unroll
        for (int it = 0; it < 4; it++)
            ureg[it] = *(const float4*)&g_Uttf[(size_t)(ukr + it * 8) * D + dB + uc4 * 4];

        for (int mt = 0; mt < 4; mt++) {
            __syncthreads();   // also covers Z->ys visibility / prev epilogue
#pragma unroll
            for (int it = 0; it < 4; it++)
                *(float4*)&us[(ukr + it * 8) * US + uc4 * 4] = ureg[it];
            __syncthreads();
            if (mt + 1 < 4) {
#pragma unroll
                for (int it = 0; it < 4; it++)
                    ureg[it] = *(const float4*)&g_Uttf[(size_t)((mt + 1) * 32 + ukr + it * 8) * D +
                                                       dB + uc4 * 4];
            }
#pragma unroll
            for (int k8 = 0; k8 < 4; k8++) {
                const int kb = k8 * 8;
                const int kg = mt * 32 + kb;
                unsigned A[4][4], B[4][2];
#pragma unroll
                for (int mf = 0; mf < 4; mf++) {
                    int r = wrow + mf * 16 + grp;
                    A[mf][0] = ysu[r * YS + kg + tg];
                    A[mf][1] = ysu[(r + 8) * YS + kg + tg];
                    A[mf][2] = ysu[r * YS + kg + tg + 4];
                    A[mf][3] = ysu[(r + 8) * YS + kg + tg + 4];
                }
#pragma unroll
                for (int nf = 0; nf < 4; nf++) {
                    int c = wcol + nf * 8 + grp;
                    B[nf][0] = usu[(kb + tg) * US + c];
                    B[nf][1] = usu[(kb + tg + 4) * US + c];
                }
#pragma unroll
                for (int mf = 0; mf < 4; mf++)
#pragma unroll
                    for (int nf = 0; nf < 4; nf++)
                        mma8(acc[mf][nf], A[mf], B[nf]);
            }
        }

        // epilogue: out = x + b - acc
#pragma unroll
        for (int mf = 0; mf < 4; mf++)
#pragma unroll
            for (int nf = 0; nf < 4; nf++) {
                int r = rowBase + wrow + mf * 16 + grp;
                int c = dB + wcol + nf * 8 + tg * 2;
                float2 bv = *(const float2*)&bias[c];
                float2 x0 = *(const float2*)&x[(size_t)r * D + c];
                float2 x1 = *(const float2*)&x[(size_t)(r + 8) * D + c];
                float2 o0, o1;
                o0.x = x0.x + bv.x - acc[mf][nf][0];
                o0.y = x0.y + bv.y - acc[mf][nf][1];
                o1.x = x1.x + bv.x - acc[mf][nf][2];
                o1.y = x1.y + bv.y - acc[mf][nf][3];
                *(float2*)&out[(size_t)r * D + c]       = o0;
                *(float2*)&out[(size_t)(r + 8) * D + c] = o1;
            }
    }
}

// ---------------------------------------------------------------------------
extern "C" void kernel_launch(void* const* d_in, const int* in_sizes, int n_in,
                              void* d_out, int out_size) {
    const float* x = nullptr;
    const float* v = nullptr;
    const float* b = nullptr;
    for (int i = 0; i < n_in; i++) {
        if      (in_sizes[i] == BATCH * D) x = (const float*)d_in[i];
        else if (in_sizes[i] == D * NV)    v = (const float*)d_in[i];
        else if (in_sizes[i] == D)         b = (const float*)d_in[i];
    }
    float* out = (float*)d_out;

    const size_t smemM     = 2 * 128 * 129 * sizeof(float);           // 132 KB
    const size_t smemFused = (4608 + 4352 + 16896) * sizeof(float);   // ~103.4 KB
    cudaFuncSetAttribute(k_buildM, cudaFuncAttributeMaxDynamicSharedMemorySize, (int)smemM);
    cudaFuncSetAttribute(k_fused,  cudaFuncAttributeMaxDynamicSharedMemorySize, (int)smemFused);

    k_colsq <<<128, 128>>>(v);
    k_prep  <<<dim3(8, 4), dim3(32, 8)>>>(v);
    k_gram  <<<dim3(16, 8), 128>>>();
    k_buildM<<<1, 128, smemM>>>();
    k_fused <<<BATCH / 128, 256, smemFused>>>(x, b, out);
}

// round 5
// speedup vs baseline: 1.3946x; 1.2594x over previous
#include <cuda_runtime.h>
#include <math.h>

#define D     1024
#define NV    128
#define BATCH 32768

// Scratch (static device globals)
__device__ float g_Utf [D * NV];      // tf32 bits of normalized U   (stage1 B)
__device__ float g_Uttf[NV * D];      // tf32 bits of U^T            (stage3 B)
__device__ float g_csq [128 * NV];    // column sum-of-squares partials [blk][col]
__device__ float g_Gp  [8 * NV * NV]; // Gram partials (K-split by 8)
__device__ float g_Mtf [NV * NV];     // tf32 bits of M = 2T

__device__ __forceinline__ unsigned f2tf(float f) {
    unsigned r;
    asm("cvt.rna.tf32.f32 %0, %1;" : "=r"(r) : "f"(f));
    return r;
}

// ---------------------------------------------------------------------------
// Setup A: column sum-of-squares partials. grid 128, block 128.
// ---------------------------------------------------------------------------
__global__ void k_colsq(const float* __restrict__ v) {
    const int col = threadIdx.x;
    const int r0  = blockIdx.x * 8;
    float s = 0.f;
#pragma unroll
    for (int r = 0; r < 8; r++) {
        float t = v[(r0 + r) * NV + col];
        s += t * t;
    }
    g_csq[blockIdx.x * NV + col] = s;
}

// ---------------------------------------------------------------------------
// Setup B: normalize + tf32-convert + transpose. grid (8,4), block (32,8).
// ---------------------------------------------------------------------------
__global__ void k_prep(const float* __restrict__ v) {
    const int tx = threadIdx.x, ty = threadIdx.y;
    const int tid = ty * 32 + tx;
    const int d0 = blockIdx.x * 128;
    const int k0 = blockIdx.y * 32;

    __shared__ float part[8][33];
    __shared__ float sinv[32];
    __shared__ float tile[32 * 137];

    float ps = 0.f;
    for (int s = ty; s < 128; s += 8) ps += g_csq[s * NV + k0 + tx];
    part[ty][tx] = ps;
    __syncthreads();
    if (ty == 0) {
        float tot = 0.f;
#pragma unroll
        for (int q = 0; q < 8; q++) tot += part[q][tx];
        sinv[tx] = rsqrtf(tot);
    }
    __syncthreads();
    const float inv = sinv[tx];

#pragma unroll
    for (int rr = 0; rr < 16; rr++) {
        int dd = ty * 16 + rr;
        int d  = d0 + dd;
        float u = v[d * NV + k0 + tx] * inv;
        float ub = __uint_as_float(f2tf(u));
        g_Utf[d * NV + k0 + tx] = ub;
        tile[tx * 137 + dd] = ub;
    }
    __syncthreads();

    for (int e = tid; e < 32 * 128; e += 256) {
        int kl = e >> 7, dd = e & 127;
        g_Uttf[(size_t)(k0 + kl) * D + d0 + dd] = tile[kl * 137 + dd];
    }
}

// ---------------------------------------------------------------------------
// Setup C: Gram partials G = Utf^T Utf. grid (16, 8), 128 threads.
// ---------------------------------------------------------------------------
__global__ void k_gram() {
    const int i  = threadIdx.x;
    const int jb = blockIdx.x * 8;
    const int s  = blockIdx.y;
    float acc[8] = {0, 0, 0, 0, 0, 0, 0, 0};
    const int d0 = s * 128;
#pragma unroll 2
    for (int d = d0; d < d0 + 128; d++) {
        float ui = g_Utf[d * NV + i];
#pragma unroll
        for (int q = 0; q < 8; q++) acc[q] += ui * g_Utf[d * NV + jb + q];
    }
#pragma unroll
    for (int q = 0; q < 8; q++) g_Gp[s * NV * NV + i * NV + jb + q] = acc[q];
}

// ---------------------------------------------------------------------------
// Setup D: M = 2 * W^{-1}, where W = I + 2*strictupper(G) (unit upper-tri).
// Blocked triangular inverse, single CTA of 128 threads:
//   1. invert 4 diagonal 32x32 blocks, one warp each (lane reads ONLY its
//      own row of X -> zero sync, serial depth 31)
//   2. combine 32->64 : X12 = -X11 (W12 X22),  two pairs in parallel
//   3. combine 64->128: same at 64x64
// ---------------------------------------------------------------------------
__global__ void k_buildM() {
    extern __shared__ float sm[];
    float* sW = sm;                    // 128*129: 2*G (upper used)
    float* sX = sm + 128 * 129;        // 128*129: result T
    float* sP = sm + 2 * 128 * 129;    // 64*65 scratch
    const int tid = threadIdx.x;

    // load W = 2*G (sum the 8 partials), init X = I
    for (int idx = tid; idx < NV * NV; idx += 128) {
        int r = idx >> 7, c = idx & 127;
        float g = 0.f;
#pragma unroll
        for (int s = 0; s < 8; s++) g += g_Gp[s * NV * NV + idx];
        sW[r * 129 + c] = 2.f * g;
        sX[r * 129 + c] = (r == c) ? 1.f : 0.f;
    }
    __syncthreads();

    // ---- step 1: invert diagonal 32x32 blocks (warp w -> block w) ----
    {
        const int w = tid >> 5;          // block
        const int t = tid & 31;          // row within block
        const int b = w * 32;
        float* xrow = &sX[(b + t) * 129 + b];   // local row t of X block
        const float* wcol = &sW[b * 129 + b];   // block of W
        for (int m = 1; m < 32; m++) {
            if (t < m) {
                float acc = 0.f;
                for (int j = t; j < m; j++)
                    acc += xrow[j] * wcol[j * 129 + m];
                xrow[m] = -acc;
            }
        }
    }
    __syncthreads();

    // ---- step 2: combine 32 -> 64 (two pairs in parallel) ----
    {
        const int p  = tid >> 6;         // pair 0 / 1
        const int tl = tid & 63;
        const int b1 = p * 64, b2 = p * 64 + 32;
        float* P = &sP[p * 32 * 33];

        // P = W12 * X22   (32x32, k=32)
#pragma unroll
        for (int i = 0; i < 16; i++) {
            int idx = tl + i * 64;
            int r = idx >> 5, c = idx & 31;
            float acc = 0.f;
#pragma unroll 4
            for (int k = 0; k < 32; k++)
                acc += sW[(b1 + r) * 129 + b2 + k] * sX[(b2 + k) * 129 + b2 + c];
            P[r * 33 + c] = acc;
        }
        __syncthreads();

        // X12 = -X11 * P
#pragma unroll
        for (int i = 0; i < 16; i++) {
            int idx = tl + i * 64;
            int r = idx >> 5, c = idx & 31;
            float acc = 0.f;
#pragma unroll 4
            for (int k = 0; k < 32; k++)
                acc += sX[(b1 + r) * 129 + b1 + k] * P[k * 33 + c];
            sX[(b1 + r) * 129 + b2 + c] = -acc;
        }
    }
    __syncthreads();

    // ---- step 3: combine 64 -> 128 ----
    {
        const int ty = tid >> 3;         // 0..15 -> 4 rows each
        const int tx = tid & 7;          // 0..7  -> 8 cols each
        const int r0 = ty * 4, c0 = tx * 8;

        // P = W12 * X22   (64x64, k=64), register-tiled 4x8
        float acc[4][8];
#pragma unroll
        for (int r = 0; r < 4; r++)
#pragma unroll
            for (int c = 0; c < 8; c++) acc[r][c] = 0.f;
#pragma unroll 2
        for (int k = 0; k < 64; k++) {
            float a[4], bv[8];
#pragma unroll
            for (int r = 0; r < 4; r++) a[r] = sW[(r0 + r) * 129 + 64 + k];
#pragma unroll
            for (int c = 0; c < 8; c++) bv[c] = sX[(64 + k) * 129 + 64 + c0 + c];
#pragma unroll
            for (int r = 0; r < 4; r++)
#pragma unroll
                for (int c = 0; c < 8; c++) acc[r][c] += a[r] * bv[c];
        }
#pragma unroll
        for (int r = 0; r < 4; r++)
#pragma unroll
            for (int c = 0; c < 8; c++) sP[(r0 + r) * 65 + c0 + c] = acc[r][c];
        __syncthreads();

        // X12 = -X11 * P   (64x64, k=64)
#pragma unroll
        for (int r = 0; r < 4; r++)
#pragma unroll
            for (int c = 0; c < 8; c++) acc[r][c] = 0.f;
#pragma unroll 2
        for (int k = 0; k < 64; k++) {
            float a[4], bv[8];
#pragma unroll
            for (int r = 0; r < 4; r++) a[r] = sX[(r0 + r) * 129 + k];
#pragma unroll
            for (int c = 0; c < 8; c++) bv[c] = sP[k * 65 + c0 + c];
#pragma unroll
            for (int r = 0; r < 4; r++)
#pragma unroll
                for (int c = 0; c < 8; c++) acc[r][c] += a[r] * bv[c];
        }
#pragma unroll
        for (int r = 0; r < 4; r++)
#pragma unroll
            for (int c = 0; c < 8; c++)
                sX[(r0 + r) * 129 + 64 + c0 + c] = -acc[r][c];
    }
    __syncthreads();

    // ---- write M = 2*X as tf32 bits ----
    for (int idx = tid; idx < NV * NV; idx += 128) {
        int r = idx >> 7, c = idx & 127;
        g_Mtf[idx] = __uint_as_float(f2tf(2.f * sX[r * 129 + c]));
    }
}

// ---------------------------------------------------------------------------
// Fused tensor-core kernel (tf32 mma m16n8k8), all operands pre-converted,
// all B-tiles prefetched behind compute.
// ---------------------------------------------------------------------------
#define XS 36
#define US 136
#define YS 132

__device__ __forceinline__ void mma8(float c[4], const unsigned a[4], const unsigned b[2]) {
    asm volatile(
        "mma.sync.aligned.m16n8k8.row.col.f32.tf32.tf32.f32 "
        "{%0,%1,%2,%3}, {%4,%5,%6,%7}, {%8,%9}, {%0,%1,%2,%3};"
        : "+f"(c[0]), "+f"(c[1]), "+f"(c[2]), "+f"(c[3])
        : "r"(a[0]), "r"(a[1]), "r"(a[2]), "r"(a[3]), "r"(b[0]), "r"(b[1]));
}

__global__ __launch_bounds__(256, 2) void k_fused(const float* __restrict__ x,
                                                  const float* __restrict__ bias,
                                                  float* __restrict__ out) {
    extern __shared__ float smf[];
    float* xs = smf;              // 128*36  = 4608
    float* us = smf + 4608;       // 32*136  = 4352
    float* ys = smf + 8960;       // 128*132 = 16896

    const int tid  = threadIdx.x;
    const int lane = tid & 31, wid = tid >> 5;
    const int wm = wid >> 2, wn = wid & 3;
    const int grp = lane >> 2, tg = lane & 3;
    const int rowBase = blockIdx.x * 128;
    const int wrow = wm * 64;
    const int wcol = wn * 32;

    const unsigned* xsu = (const unsigned*)xs;
    const unsigned* usu = (const unsigned*)us;
    const unsigned* ysu = (const unsigned*)ys;

    float acc[4][4][4];
    const int xr0 = tid >> 3, xc4 = tid & 7;
    const int ukr = tid >> 5, uc4 = tid & 31;

    // ======== Stage 1: Y = x @ U ========
#pragma unroll
    for (int mf = 0; mf < 4; mf++)
#pragma unroll
        for (int nf = 0; nf < 4; nf++)
#pragma unroll
            for (int q = 0; q < 4; q++) acc[mf][nf][q] = 0.f;

    float4 p[4], ureg[4];
#pragma unroll
    for (int it = 0; it < 4; it++) {
        p[it] = *(const float4*)&x[(size_t)(rowBase + xr0 + it * 32) * D + xc4 * 4];
        ureg[it] = *(const float4*)&g_Utf[(ukr + it * 8) * NV + uc4 * 4];
    }

    for (int kt = 0; kt < D / 32; kt++) {
#pragma unroll
        for (int it = 0; it < 4; it++) {
            uint4 t;
            t.x = f2tf(p[it].x); t.y = f2tf(p[it].y);
            t.z = f2tf(p[it].z); t.w = f2tf(p[it].w);
            *(uint4*)&xs[(xr0 + it * 32) * XS + xc4 * 4] = t;
        }
#pragma unroll
        for (int it = 0; it < 4; it++)
            *(float4*)&us[(ukr + it * 8) * US + uc4 * 4] = ureg[it];
        __syncthreads();
        if (kt + 1 < D / 32) {
#pragma unroll
            for (int it = 0; it < 4; it++) {
                p[it] = *(const float4*)&x[(size_t)(rowBase + xr0 + it * 32) * D +
                                           (kt + 1) * 32 + xc4 * 4];
                ureg[it] = *(const float4*)&g_Utf[((kt + 1) * 32 + ukr + it * 8) * NV + uc4 * 4];
            }
        }
#pragma unroll
        for (int k8 = 0; k8 < 4; k8++) {
            const int kb = k8 * 8;
            unsigned A[4][4], B[4][2];
#pragma unroll
            for (int mf = 0; mf < 4; mf++) {
                int r = wrow + mf * 16 + grp;
                A[mf][0] = xsu[r * XS + kb + tg];
                A[mf][1] = xsu[(r + 8) * XS + kb + tg];
                A[mf][2] = xsu[r * XS + kb + tg + 4];
                A[mf][3] = xsu[(r + 8) * XS + kb + tg + 4];
            }
#pragma unroll
            for (int nf = 0; nf < 4; nf++) {
                int c = wcol + nf * 8 + grp;
                B[nf][0] = usu[(kb + tg) * US + c];
                B[nf][1] = usu[(kb + tg + 4) * US + c];
            }
#pragma unroll
            for (int mf = 0; mf < 4; mf++)
#pragma unroll
                for (int nf = 0; nf < 4; nf++)
                    mma8(acc[mf][nf], A[mf], B[nf]);
        }
        __syncthreads();
    }

    // Y -> ys (tf32 bits)
#pragma unroll
    for (int mf = 0; mf < 4; mf++)
#pragma unroll
        for (int nf = 0; nf < 4; nf++) {
            int r = wrow + mf * 16 + grp, c = wcol + nf * 8 + tg * 2;
            ys[r * YS + c]           = __uint_as_float(f2tf(acc[mf][nf][0]));
            ys[r * YS + c + 1]       = __uint_as_float(f2tf(acc[mf][nf][1]));
            ys[(r + 8) * YS + c]     = __uint_as_float(f2tf(acc[mf][nf][2]));
            ys[(r + 8) * YS + c + 1] = __uint_as_float(f2tf(acc[mf][nf][3]));
        }

    // ======== Stage 2: Z = Y @ M ========
#pragma unroll
    for (int mf = 0; mf < 4; mf++)
#pragma unroll
        for (int nf = 0; nf < 4; nf++)
#pragma unroll
            for (int q = 0; q < 4; q++) acc[mf][nf][q] = 0.f;

#pragma unroll
    for (int it = 0; it < 4; it++)
        ureg[it] = *(const float4*)&g_Mtf[(ukr + it * 8) * NV + uc4 * 4];

    for (int mt = 0; mt < 4; mt++) {
        __syncthreads();
#pragma unroll
        for (int it = 0; it < 4; it++)
            *(float4*)&us[(ukr + it * 8) * US + uc4 * 4] = ureg[it];
        __syncthreads();
        if (mt + 1 < 4) {
#pragma unroll
            for (int it = 0; it < 4; it++)
                ureg[it] = *(const float4*)&g_Mtf[((mt + 1) * 32 + ukr + it * 8) * NV + uc4 * 4];
        }
#pragma unroll
        for (int k8 = 0; k8 < 4; k8++) {
            const int kb = k8 * 8;
            const int kg = mt * 32 + kb;
            unsigned A[4][4], B[4][2];
#pragma unroll
            for (int mf = 0; mf < 4; mf++) {
                int r = wrow + mf * 16 + grp;
                A[mf][0] = ysu[r * YS + kg + tg];
                A[mf][1] = ysu[(r + 8) * YS + kg + tg];
                A[mf][2] = ysu[r * YS + kg + tg + 4];
                A[mf][3] = ysu[(r + 8) * YS + kg + tg + 4];
            }
#pragma unroll
            for (int nf = 0; nf < 4; nf++) {
                int c = wcol + nf * 8 + grp;
                B[nf][0] = usu[(kb + tg) * US + c];
                B[nf][1] = usu[(kb + tg + 4) * US + c];
            }
#pragma unroll
            for (int mf = 0; mf < 4; mf++)
#pragma unroll
                for (int nf = 0; nf < 4; nf++)
                    mma8(acc[mf][nf], A[mf], B[nf]);
        }
    }
    __syncthreads();

    // Z overwrites Y (tf32 bits)
#pragma unroll
    for (int mf = 0; mf < 4; mf++)
#pragma unroll
        for (int nf = 0; nf < 4; nf++) {
            int r = wrow + mf * 16 + grp, c = wcol + nf * 8 + tg * 2;
            ys[r * YS + c]           = __uint_as_float(f2tf(acc[mf][nf][0]));
            ys[r * YS + c + 1]       = __uint_as_float(f2tf(acc[mf][nf][1]));
            ys[(r + 8) * YS + c]     = __uint_as_float(f2tf(acc[mf][nf][2]));
            ys[(r + 8) * YS + c + 1] = __uint_as_float(f2tf(acc[mf][nf][3]));
        }

    // ======== Stage 3: out = x - Z @ U^T + b ========
    for (int dB = 0; dB < D; dB += 128) {
#pragma unroll
        for (int mf = 0; mf < 4; mf++)
#pragma unroll
            for (int nf = 0; nf < 4; nf++)
#pragma unroll
                for (int q = 0; q < 4; q++) acc[mf][nf][q] = 0.f;

#pragma unroll
        for (int it = 0; it < 4; it++)
            ureg[it] = *(const float4*)&g_Uttf[(size_t)(ukr + it * 8) * D + dB + uc4 * 4];

        for (int mt = 0; mt < 4; mt++) {
            __syncthreads();
#pragma unroll
            for (int it = 0; it < 4; it++)
                *(float4*)&us[(ukr + it * 8) * US + uc4 * 4] = ureg[it];
            __syncthreads();
            if (mt + 1 < 4) {
#pragma unroll
                for (int it = 0; it < 4; it++)
                    ureg[it] = *(const float4*)&g_Uttf[(size_t)((mt + 1) * 32 + ukr + it * 8) * D +
                                                       dB + uc4 * 4];
            }
#pragma unroll
            for (int k8 = 0; k8 < 4; k8++) {
                const int kb = k8 * 8;
                const int kg = mt * 32 + kb;
                unsigned A[4][4], B[4][2];
#pragma unroll
                for (int mf = 0; mf < 4; mf++) {
                    int r = wrow + mf * 16 + grp;
                    A[mf][0] = ysu[r * YS + kg + tg];
                    A[mf][1] = ysu[(r + 8) * YS + kg + tg];
                    A[mf][2] = ysu[r * YS + kg + tg + 4];
                    A[mf][3] = ysu[(r + 8) * YS + kg + tg + 4];
                }
#pragma unroll
                for (int nf = 0; nf < 4; nf++) {
                    int c = wcol + nf * 8 + grp;
                    B[nf][0] = usu[(kb + tg) * US + c];
                    B[nf][1] = usu[(kb + tg + 4) * US + c];
                }
#pragma unroll
                for (int mf = 0; mf < 4; mf++)
#pragma unroll
                    for (int nf = 0; nf < 4; nf++)
                        mma8(acc[mf][nf], A[mf], B[nf]);
            }
        }

        // epilogue: out = x + b - acc
#pragma unroll
        for (int mf = 0; mf < 4; mf++)
#pragma unroll
            for (int nf = 0; nf < 4; nf++) {
                int r = rowBase + wrow + mf * 16 + grp;
                int c = dB + wcol + nf * 8 + tg * 2;
                float2 bv = *(const float2*)&bias[c];
                float2 x0 = *(const float2*)&x[(size_t)r * D + c];
                float2 x1 = *(const float2*)&x[(size_t)(r + 8) * D + c];
                float2 o0, o1;
                o0.x = x0.x + bv.x - acc[mf][nf][0];
                o0.y = x0.y + bv.y - acc[mf][nf][1];
                o1.x = x1.x + bv.x - acc[mf][nf][2];
                o1.y = x1.y + bv.y - acc[mf][nf][3];
                *(float2*)&out[(size_t)r * D + c]       = o0;
                *(float2*)&out[(size_t)(r + 8) * D + c] = o1;
            }
    }
}

// ---------------------------------------------------------------------------
extern "C" void kernel_launch(void* const* d_in, const int* in_sizes, int n_in,
                              void* d_out, int out_size) {
    const float* x = nullptr;
    const float* v = nullptr;
    const float* b = nullptr;
    for (int i = 0; i < n_in; i++) {
        if      (in_sizes[i] == BATCH * D) x = (const float*)d_in[i];
        else if (in_sizes[i] == D * NV)    v = (const float*)d_in[i];
        else if (in_sizes[i] == D)         b = (const float*)d_in[i];
    }
    float* out = (float*)d_out;

    const size_t smemM     = (2 * 128 * 129 + 64 * 65) * sizeof(float); // ~145 KB
    const size_t smemFused = (4608 + 4352 + 16896) * sizeof(float);     // ~103.4 KB
    cudaFuncSetAttribute(k_buildM, cudaFuncAttributeMaxDynamicSharedMemorySize, (int)smemM);
    cudaFuncSetAttribute(k_fused,  cudaFuncAttributeMaxDynamicSharedMemorySize, (int)smemFused);

    k_colsq <<<128, 128>>>(v);
    k_prep  <<<dim3(8, 4), dim3(32, 8)>>>(v);
    k_gram  <<<dim3(16, 8), 128>>>();
    k_buildM<<<1, 128, smemM>>>();
    k_fused <<<BATCH / 128, 256, smemFused>>>(x, b, out);
}

// round 6
// speedup vs baseline: 1.5448x; 1.1077x over previous
#include <cuda_runtime.h>
#include <math.h>

#define D     1024
#define NV    128
#define BATCH 32768

// Scratch (static device globals)
__device__ float g_Utf [D * NV];      // tf32 bits of normalized U   (stage1 B)
__device__ float g_Uttf[NV * D];      // tf32 bits of U^T            (stage3 B)
__device__ float g_csq [128 * NV];    // column sum-of-squares partials [blk][col]
__device__ float g_Gp  [8 * NV * NV]; // Gram partials (K-split by 8)
__device__ float g_Mtf [NV * NV];     // tf32 bits of M = 2T

__device__ __forceinline__ unsigned f2tf(float f) {
    unsigned r;
    asm("cvt.rna.tf32.f32 %0, %1;" : "=r"(r) : "f"(f));
    return r;
}

// ---------------------------------------------------------------------------
// Setup A: column sum-of-squares partials. grid 128, block 128.
// ---------------------------------------------------------------------------
__global__ void k_colsq(const float* __restrict__ v) {
    const int col = threadIdx.x;
    const int r0  = blockIdx.x * 8;
    float s = 0.f;
#pragma unroll
    for (int r = 0; r < 8; r++) {
        float t = v[(r0 + r) * NV + col];
        s += t * t;
    }
    g_csq[blockIdx.x * NV + col] = s;
}

// ---------------------------------------------------------------------------
// Setup B: normalize + tf32-convert + transpose. grid (8,4), block (32,8).
// ---------------------------------------------------------------------------
__global__ void k_prep(const float* __restrict__ v) {
    const int tx = threadIdx.x, ty = threadIdx.y;
    const int tid = ty * 32 + tx;
    const int d0 = blockIdx.x * 128;
    const int k0 = blockIdx.y * 32;

    __shared__ float part[8][33];
    __shared__ float sinv[32];
    __shared__ float tile[32 * 137];

    float ps = 0.f;
    for (int s = ty; s < 128; s += 8) ps += g_csq[s * NV + k0 + tx];
    part[ty][tx] = ps;
    __syncthreads();
    if (ty == 0) {
        float tot = 0.f;
#pragma unroll
        for (int q = 0; q < 8; q++) tot += part[q][tx];
        sinv[tx] = rsqrtf(tot);
    }
    __syncthreads();
    const float inv = sinv[tx];

#pragma unroll
    for (int rr = 0; rr < 16; rr++) {
        int dd = ty * 16 + rr;
        int d  = d0 + dd;
        float u = v[d * NV + k0 + tx] * inv;
        float ub = __uint_as_float(f2tf(u));
        g_Utf[d * NV + k0 + tx] = ub;
        tile[tx * 137 + dd] = ub;
    }
    __syncthreads();

    for (int e = tid; e < 32 * 128; e += 256) {
        int kl = e >> 7, dd = e & 127;
        g_Uttf[(size_t)(k0 + kl) * D + d0 + dd] = tile[kl * 137 + dd];
    }
}

// ---------------------------------------------------------------------------
// Setup C: Gram partials G = Utf^T Utf. grid (16, 8), 128 threads.
// ---------------------------------------------------------------------------
__global__ void k_gram() {
    const int i  = threadIdx.x;
    const int jb = blockIdx.x * 8;
    const int s  = blockIdx.y;
    float acc[8] = {0, 0, 0, 0, 0, 0, 0, 0};
    const int d0 = s * 128;
#pragma unroll 2
    for (int d = d0; d < d0 + 128; d++) {
        float ui = g_Utf[d * NV + i];
#pragma unroll
        for (int q = 0; q < 8; q++) acc[q] += ui * g_Utf[d * NV + jb + q];
    }
#pragma unroll
    for (int q = 0; q < 8; q++) g_Gp[s * NV * NV + i * NV + jb + q] = acc[q];
}

// ---------------------------------------------------------------------------
// Setup D: M = 2 * W^{-1}, W = I + 2*strictupper(G). Single CTA, 256 threads.
//   step 1: 4 diagonal 32x32 inverses, one warp each, REGISTER-RESIDENT rows,
//           fully unrolled (496 static FMAs, W reads are warp-broadcast LDS)
//   step 2: combine 32->64 (two pairs), 256 threads
//   step 3: combine 64->128, 256 threads, 4x4 register tiles
// ---------------------------------------------------------------------------
__global__ void k_buildM() {
    extern __shared__ float sm[];
    float* sW = sm;                    // 128*129
    float* sX = sm + 128 * 129;        // 128*129
    float* sP = sm + 2 * 128 * 129;    // 64*65 scratch
    const int tid = threadIdx.x;       // 256 threads

    // load W = 2*G (sum 8 partials), init X = I
    for (int idx = tid; idx < NV * NV; idx += 256) {
        int r = idx >> 7, c = idx & 127;
        float g = 0.f;
#pragma unroll
        for (int s = 0; s < 8; s++) g += g_Gp[s * NV * NV + idx];
        sW[r * 129 + c] = 2.f * g;
        sX[r * 129 + c] = (r == c) ? 1.f : 0.f;
    }
    __syncthreads();

    // ---- step 1: diagonal 32x32 inverses (warps 0..3), register rows ----
    if (tid < 128) {
        const int w = tid >> 5;          // block index
        const int t = tid & 31;          // row within block
        const int b = w * 32;
        const float* Wb = &sW[b * 129 + b];

        float xr[32];
#pragma unroll
        for (int j = 0; j < 32; j++) xr[j] = (j == t) ? 1.f : 0.f;

#pragma unroll
        for (int m = 1; m < 32; m++) {
            float acc = 0.f;
#pragma unroll
            for (int j = 0; j < m; j++)
                acc += xr[j] * Wb[j * 129 + m];   // xr[j]=0 for j<t folds out
            xr[m] = (t < m) ? -acc : xr[m];
        }
        float* Xb = &sX[(b + t) * 129 + b];
#pragma unroll
        for (int j = 0; j < 32; j++) Xb[j] = xr[j];
    }
    __syncthreads();

    // ---- step 2: combine 32 -> 64 (two pairs in parallel, 128 thr each) ----
    {
        const int p  = tid >> 7;         // pair 0 / 1
        const int tl = tid & 127;
        const int b1 = p * 64, b2 = p * 64 + 32;
        float* P = &sP[p * 32 * 33];

        // P = W12 * X22   (32x32, k=32)
#pragma unroll
        for (int i = 0; i < 8; i++) {
            int idx = tl + i * 128;
            int r = idx >> 5, c = idx & 31;
            float acc = 0.f;
#pragma unroll 8
            for (int k = 0; k < 32; k++)
                acc += sW[(b1 + r) * 129 + b2 + k] * sX[(b2 + k) * 129 + b2 + c];
            P[r * 33 + c] = acc;
        }
        __syncthreads();

        // X12 = -X11 * P
#pragma unroll
        for (int i = 0; i < 8; i++) {
            int idx = tl + i * 128;
            int r = idx >> 5, c = idx & 31;
            float acc = 0.f;
#pragma unroll 8
            for (int k = 0; k < 32; k++)
                acc += sX[(b1 + r) * 129 + b1 + k] * P[k * 33 + c];
            sX[(b1 + r) * 129 + b2 + c] = -acc;
        }
    }
    __syncthreads();

    // ---- step 3: combine 64 -> 128 (256 threads, 4x4 register tiles) ----
    {
        const int ty = tid >> 4;         // 0..15 -> 4 rows each
        const int tx = tid & 15;         // 0..15 -> 4 cols each
        const int r0 = ty * 4, c0 = tx * 4;

        // P = W12 * X22   (64x64, k=64)
        float acc[4][4];
#pragma unroll
        for (int r = 0; r < 4; r++)
#pragma unroll
            for (int c = 0; c < 4; c++) acc[r][c] = 0.f;
#pragma unroll 4
        for (int k = 0; k < 64; k++) {
            float a[4], bv[4];
#pragma unroll
            for (int r = 0; r < 4; r++) a[r] = sW[(r0 + r) * 129 + 64 + k];
#pragma unroll
            for (int c = 0; c < 4; c++) bv[c] = sX[(64 + k) * 129 + 64 + c0 + c];
#pragma unroll
            for (int r = 0; r < 4; r++)
#pragma unroll
                for (int c = 0; c < 4; c++) acc[r][c] += a[r] * bv[c];
        }
#pragma unroll
        for (int r = 0; r < 4; r++)
#pragma unroll
            for (int c = 0; c < 4; c++) sP[(r0 + r) * 65 + c0 + c] = acc[r][c];
        __syncthreads();

        // X12 = -X11 * P   (64x64, k=64)
#pragma unroll
        for (int r = 0; r < 4; r++)
#pragma unroll
            for (int c = 0; c < 4; c++) acc[r][c] = 0.f;
#pragma unroll 4
        for (int k = 0; k < 64; k++) {
            float a[4], bv[4];
#pragma unroll
            for (int r = 0; r < 4; r++) a[r] = sX[(r0 + r) * 129 + k];
#pragma unroll
            for (int c = 0; c < 4; c++) bv[c] = sP[k * 65 + c0 + c];
#pragma unroll
            for (int r = 0; r < 4; r++)
#pragma unroll
                for (int c = 0; c < 4; c++) acc[r][c] += a[r] * bv[c];
        }
#pragma unroll
        for (int r = 0; r < 4; r++)
#pragma unroll
            for (int c = 0; c < 4; c++)
                sX[(r0 + r) * 129 + 64 + c0 + c] = -acc[r][c];
    }
    __syncthreads();

    // ---- write M = 2*X as tf32 bits ----
    for (int idx = tid; idx < NV * NV; idx += 256) {
        int r = idx >> 7, c = idx & 127;
        g_Mtf[idx] = __uint_as_float(f2tf(2.f * sX[r * 129 + c]));
    }
}

// ---------------------------------------------------------------------------
// Fused tensor-core kernel (tf32 mma m16n8k8), all operands pre-converted,
// all B-tiles prefetched behind compute.
// ---------------------------------------------------------------------------
#define XS 36
#define US 136
#define YS 132

__device__ __forceinline__ void mma8(float c[4], const unsigned a[4], const unsigned b[2]) {
    asm volatile(
        "mma.sync.aligned.m16n8k8.row.col.f32.tf32.tf32.f32 "
        "{%0,%1,%2,%3}, {%4,%5,%6,%7}, {%8,%9}, {%0,%1,%2,%3};"
        : "+f"(c[0]), "+f"(c[1]), "+f"(c[2]), "+f"(c[3])
        : "r"(a[0]), "r"(a[1]), "r"(a[2]), "r"(a[3]), "r"(b[0]), "r"(b[1]));
}

__global__ __launch_bounds__(256, 2) void k_fused(const float* __restrict__ x,
                                                  const float* __restrict__ bias,
                                                  float* __restrict__ out) {
    extern __shared__ float smf[];
    float* xs = smf;              // 128*36  = 4608
    float* us = smf + 4608;       // 32*136  = 4352
    float* ys = smf + 8960;       // 128*132 = 16896

    const int tid  = threadIdx.x;
    const int lane = tid & 31, wid = tid >> 5;
    const int wm = wid >> 2, wn = wid & 3;
    const int grp = lane >> 2, tg = lane & 3;
    const int rowBase = blockIdx.x * 128;
    const int wrow = wm * 64;
    const int wcol = wn * 32;

    const unsigned* xsu = (const unsigned*)xs;
    const unsigned* usu = (const unsigned*)us;
    const unsigned* ysu = (const unsigned*)ys;

    float acc[4][4][4];
    const int xr0 = tid >> 3, xc4 = tid & 7;
    const int ukr = tid >> 5, uc4 = tid & 31;

    // ======== Stage 1: Y = x @ U ========
#pragma unroll
    for (int mf = 0; mf < 4; mf++)
#pragma unroll
        for (int nf = 0; nf < 4; nf++)
#pragma unroll
            for (int q = 0; q < 4; q++) acc[mf][nf][q] = 0.f;

    float4 p[4], ureg[4];
#pragma unroll
    for (int it = 0; it < 4; it++) {
        p[it] = *(const float4*)&x[(size_t)(rowBase + xr0 + it * 32) * D + xc4 * 4];
        ureg[it] = *(const float4*)&g_Utf[(ukr + it * 8) * NV + uc4 * 4];
    }

    for (int kt = 0; kt < D / 32; kt++) {
#pragma unroll
        for (int it = 0; it < 4; it++) {
            uint4 t;
            t.x = f2tf(p[it].x); t.y = f2tf(p[it].y);
            t.z = f2tf(p[it].z); t.w = f2tf(p[it].w);
            *(uint4*)&xs[(xr0 + it * 32) * XS + xc4 * 4] = t;
        }
#pragma unroll
        for (int it = 0; it < 4; it++)
            *(float4*)&us[(ukr + it * 8) * US + uc4 * 4] = ureg[it];
        __syncthreads();
        if (kt + 1 < D / 32) {
#pragma unroll
            for (int it = 0; it < 4; it++) {
                p[it] = *(const float4*)&x[(size_t)(rowBase + xr0 + it * 32) * D +
                                           (kt + 1) * 32 + xc4 * 4];
                ureg[it] = *(const float4*)&g_Utf[((kt + 1) * 32 + ukr + it * 8) * NV + uc4 * 4];
            }
        }
#pragma unroll
        for (int k8 = 0; k8 < 4; k8++) {
            const int kb = k8 * 8;
            unsigned A[4][4], B[4][2];
#pragma unroll
            for (int mf = 0; mf < 4; mf++) {
                int r = wrow + mf * 16 + grp;
                A[mf][0] = xsu[r * XS + kb + tg];
                A[mf][1] = xsu[(r + 8) * XS + kb + tg];
                A[mf][2] = xsu[r * XS + kb + tg + 4];
                A[mf][3] = xsu[(r + 8) * XS + kb + tg + 4];
            }
#pragma unroll
            for (int nf = 0; nf < 4; nf++) {
                int c = wcol + nf * 8 + grp;
                B[nf][0] = usu[(kb + tg) * US + c];
                B[nf][1] = usu[(kb + tg + 4) * US + c];
            }
#pragma unroll
            for (int mf = 0; mf < 4; mf++)
#pragma unroll
                for (int nf = 0; nf < 4; nf++)
                    mma8(acc[mf][nf], A[mf], B[nf]);
        }
        __syncthreads();
    }

    // Y -> ys (tf32 bits)
#pragma unroll
    for (int mf = 0; mf < 4; mf++)
#pragma unroll
        for (int nf = 0; nf < 4; nf++) {
            int r = wrow + mf * 16 + grp, c = wcol + nf * 8 + tg * 2;
            ys[r * YS + c]           = __uint_as_float(f2tf(acc[mf][nf][0]));
            ys[r * YS + c + 1]       = __uint_as_float(f2tf(acc[mf][nf][1]));
            ys[(r + 8) * YS + c]     = __uint_as_float(f2tf(acc[mf][nf][2]));
            ys[(r + 8) * YS + c + 1] = __uint_as_float(f2tf(acc[mf][nf][3]));
        }

    // ======== Stage 2: Z = Y @ M ========
#pragma unroll
    for (int mf = 0; mf < 4; mf++)
#pragma unroll
        for (int nf = 0; nf < 4; nf++)
#pragma unroll
            for (int q = 0; q < 4; q++) acc[mf][nf][q] = 0.f;

#pragma unroll
    for (int it = 0; it < 4; it++)
        ureg[it] = *(const float4*)&g_Mtf[(ukr + it * 8) * NV + uc4 * 4];

    for (int mt = 0; mt < 4; mt++) {
        __syncthreads();
#pragma unroll
        for (int it = 0; it < 4; it++)
            *(float4*)&us[(ukr + it * 8) * US + uc4 * 4] = ureg[it];
        __syncthreads();
        if (mt + 1 < 4) {
#pragma unroll
            for (int it = 0; it < 4; it++)
                ureg[it] = *(const float4*)&g_Mtf[((mt + 1) * 32 + ukr + it * 8) * NV + uc4 * 4];
        }
#pragma unroll
        for (int k8 = 0; k8 < 4; k8++) {
            const int kb = k8 * 8;
            const int kg = mt * 32 + kb;
            unsigned A[4][4], B[4][2];
#pragma unroll
            for (int mf = 0; mf < 4; mf++) {
                int r = wrow + mf * 16 + grp;
                A[mf][0] = ysu[r * YS + kg + tg];
                A[mf][1] = ysu[(r + 8) * YS + kg + tg];
                A[mf][2] = ysu[r * YS + kg + tg + 4];
                A[mf][3] = ysu[(r + 8) * YS + kg + tg + 4];
            }
#pragma unroll
            for (int nf = 0; nf < 4; nf++) {
                int c = wcol + nf * 8 + grp;
                B[nf][0] = usu[(kb + tg) * US + c];
                B[nf][1] = usu[(kb + tg + 4) * US + c];
            }
#pragma unroll
            for (int mf = 0; mf < 4; mf++)
#pragma unroll
                for (int nf = 0; nf < 4; nf++)
                    mma8(acc[mf][nf], A[mf], B[nf]);
        }
    }
    __syncthreads();

    // Z overwrites Y (tf32 bits)
#pragma unroll
    for (int mf = 0; mf < 4; mf++)
#pragma unroll
        for (int nf = 0; nf < 4; nf++) {
            int r = wrow + mf * 16 + grp, c = wcol + nf * 8 + tg * 2;
            ys[r * YS + c]           = __uint_as_float(f2tf(acc[mf][nf][0]));
            ys[r * YS + c + 1]       = __uint_as_float(f2tf(acc[mf][nf][1]));
            ys[(r + 8) * YS + c]     = __uint_as_float(f2tf(acc[mf][nf][2]));
            ys[(r + 8) * YS + c + 1] = __uint_as_float(f2tf(acc[mf][nf][3]));
        }

    // ======== Stage 3: out = x - Z @ U^T + b ========
    for (int dB = 0; dB < D; dB += 128) {
#pragma unroll
        for (int mf = 0; mf < 4; mf++)
#pragma unroll
            for (int nf = 0; nf < 4; nf++)
#pragma unroll
                for (int q = 0; q < 4; q++) acc[mf][nf][q] = 0.f;

#pragma unroll
        for (int it = 0; it < 4; it++)
            ureg[it] = *(const float4*)&g_Uttf[(size_t)(ukr + it * 8) * D + dB + uc4 * 4];

        for (int mt = 0; mt < 4; mt++) {
            __syncthreads();
#pragma unroll
            for (int it = 0; it < 4; it++)
                *(float4*)&us[(ukr + it * 8) * US + uc4 * 4] = ureg[it];
            __syncthreads();
            if (mt + 1 < 4) {
#pragma unroll
                for (int it = 0; it < 4; it++)
                    ureg[it] = *(const float4*)&g_Uttf[(size_t)((mt + 1) * 32 + ukr + it * 8) * D +
                                                       dB + uc4 * 4];
            }
#pragma unroll
            for (int k8 = 0; k8 < 4; k8++) {
                const int kb = k8 * 8;
                const int kg = mt * 32 + kb;
                unsigned A[4][4], B[4][2];
#pragma unroll
                for (int mf = 0; mf < 4; mf++) {
                    int r = wrow + mf * 16 + grp;
                    A[mf][0] = ysu[r * YS + kg + tg];
                    A[mf][1] = ysu[(r + 8) * YS + kg + tg];
                    A[mf][2] = ysu[r * YS + kg + tg + 4];
                    A[mf][3] = ysu[(r + 8) * YS + kg + tg + 4];
                }
#pragma unroll
                for (int nf = 0; nf < 4; nf++) {
                    int c = wcol + nf * 8 + grp;
                    B[nf][0] = usu[(kb + tg) * US + c];
                    B[nf][1] = usu[(kb + tg + 4) * US + c];
                }
#pragma unroll
                for (int mf = 0; mf < 4; mf++)
#pragma unroll
                    for (int nf = 0; nf < 4; nf++)
                        mma8(acc[mf][nf], A[mf], B[nf]);
            }
        }

        // epilogue: out = x + b - acc
#pragma unroll
        for (int mf = 0; mf < 4; mf++)
#pragma unroll
            for (int nf = 0; nf < 4; nf++) {
                int r = rowBase + wrow + mf * 16 + grp;
                int c = dB + wcol + nf * 8 + tg * 2;
                float2 bv = *(const float2*)&bias[c];
                float2 x0 = *(const float2*)&x[(size_t)r * D + c];
                float2 x1 = *(const float2*)&x[(size_t)(r + 8) * D + c];
                float2 o0, o1;
                o0.x = x0.x + bv.x - acc[mf][nf][0];
                o0.y = x0.y + bv.y - acc[mf][nf][1];
                o1.x = x1.x + bv.x - acc[mf][nf][2];
                o1.y = x1.y + bv.y - acc[mf][nf][3];
                *(float2*)&out[(size_t)r * D + c]       = o0;
                *(float2*)&out[(size_t)(r + 8) * D + c] = o1;
            }
    }
}

// ---------------------------------------------------------------------------
extern "C" void kernel_launch(void* const* d_in, const int* in_sizes, int n_in,
                              void* d_out, int out_size) {
    const float* x = nullptr;
    const float* v = nullptr;
    const float* b = nullptr;
    for (int i = 0; i < n_in; i++) {
        if      (in_sizes[i] == BATCH * D) x = (const float*)d_in[i];
        else if (in_sizes[i] == D * NV)    v = (const float*)d_in[i];
        else if (in_sizes[i] == D)         b = (const float*)d_in[i];
    }
    float* out = (float*)d_out;

    const size_t smemM     = (2 * 128 * 129 + 64 * 65) * sizeof(float); // ~145 KB
    const size_t smemFused = (4608 + 4352 + 16896) * sizeof(float);     // ~103.4 KB
    cudaFuncSetAttribute(k_buildM, cudaFuncAttributeMaxDynamicSharedMemorySize, (int)smemM);
    cudaFuncSetAttribute(k_fused,  cudaFuncAttributeMaxDynamicSharedMemorySize, (int)smemFused);

    k_colsq <<<128, 128>>>(v);
    k_prep  <<<dim3(8, 4), dim3(32, 8)>>>(v);
    k_gram  <<<dim3(16, 8), 128>>>();
    k_buildM<<<1, 256, smemM>>>();
    k_fused <<<BATCH / 128, 256, smemFused>>>(x, b, out);
}